// round 1
// baseline (speedup 1.0000x reference)
#include <cuda_runtime.h>

#define B_ 256
#define L_ 2048
#define H_ 240
#define NSPLIT 8

// Static scratch (allocation-free rule): scores/alpha and split-K partials.
__device__ float g_scores[B_ * L_];                 // 2 MB
__device__ float g_vpart[NSPLIT * B_ * H_];        // 1.97 MB

// Accurate-ish fast tanh: __expf rel err ~2^-21, __fdividef ~2^-21.
// Far more accurate than tanh.approx (2^-11), and only 2 MUFU ops.
__device__ __forceinline__ float fast_tanh(float x) {
    float xc = fminf(fmaxf(x, -15.0f), 15.0f);
    float e  = __expf(2.0f * xc);
    return __fdividef(e - 1.0f, e + 1.0f);
}

// ---------------------------------------------------------------------------
// Kernel 1: scores[b,l] = sum_o tanh( (h[b,l,:] . W[o,:]) + bias[o] ) * us[b,o]
// Tiled GEMM: BM=64 rows of h, BN=240 (all outputs), BK=16.
// 256 threads = 16(tx: n-groups) x 16(ty: m-groups); thread tile 4m x 15n.
// CTAs whose l-tile is fully masked (l0 >= length[b]) exit immediately.
// ---------------------------------------------------------------------------
__global__ __launch_bounds__(256) void scores_kernel(
    const float* __restrict__ hin,
    const float* __restrict__ us,
    const float* __restrict__ W,
    const float* __restrict__ bias,
    const int*   __restrict__ len_in)
{
    const int b  = blockIdx.y;
    const int l0 = blockIdx.x * 64;
    const int len = len_in[b];
    if (l0 >= len) return;                 // fully masked tile: skip all work

    __shared__ float As[16][68];           // A^T [k][m], padded (float4-aligned reads)
    __shared__ float Bs[16][242];          // W^T [k][o], padded (bank spread)
    __shared__ float ush[H_];
    __shared__ float bsh[H_];

    const int tid = threadIdx.x;
    const int tx  = tid & 15;              // n group
    const int ty  = tid >> 4;              // m group

    if (tid < H_) {
        ush[tid] = us[b * H_ + tid];
        bsh[tid] = bias[tid];
    }

    float acc[4][15];
#pragma unroll
    for (int i = 0; i < 4; i++)
#pragma unroll
        for (int j = 0; j < 15; j++) acc[i][j] = 0.0f;

    const size_t hbase = ((size_t)b * L_ + l0) * H_;

    for (int k0 = 0; k0 < H_; k0 += 16) {
        // Load A tile: 64 rows x 16 k, one float4 per thread.
        {
            const int row = tid >> 2;       // 0..63
            const int kv  = tid & 3;        // 0..3
            const float4 av = *(const float4*)(hin + hbase + (size_t)row * H_ + k0 + kv * 4);
            As[kv * 4 + 0][row] = av.x;
            As[kv * 4 + 1][row] = av.y;
            As[kv * 4 + 2][row] = av.z;
            As[kv * 4 + 3][row] = av.w;
        }
        // Load B tile: W[o, k0..k0+15] for all 240 o, transposed into Bs[k][o].
        for (int idx = tid; idx < 960; idx += 256) {
            const int o  = idx >> 2;        // 0..239
            const int kv = idx & 3;
            const float4 wv = *(const float4*)(W + (size_t)o * H_ + k0 + kv * 4);
            Bs[kv * 4 + 0][o] = wv.x;
            Bs[kv * 4 + 1][o] = wv.y;
            Bs[kv * 4 + 2][o] = wv.z;
            Bs[kv * 4 + 3][o] = wv.w;
        }
        __syncthreads();

#pragma unroll
        for (int k = 0; k < 16; k++) {
            const float4 a4 = *(const float4*)(&As[k][ty * 4]);
            float bb[15];
#pragma unroll
            for (int j = 0; j < 15; j++) bb[j] = Bs[k][tx + 16 * j];
#pragma unroll
            for (int j = 0; j < 15; j++) {
                acc[0][j] = fmaf(a4.x, bb[j], acc[0][j]);
                acc[1][j] = fmaf(a4.y, bb[j], acc[1][j]);
                acc[2][j] = fmaf(a4.z, bb[j], acc[2][j]);
                acc[3][j] = fmaf(a4.w, bb[j], acc[3][j]);
            }
        }
        __syncthreads();
    }

    // Epilogue: bias + tanh + dot with us, reduce over n (16 tx lanes).
    float part[4] = {0.0f, 0.0f, 0.0f, 0.0f};
#pragma unroll
    for (int j = 0; j < 15; j++) {
        const int n = tx + 16 * j;
        const float uu = ush[n];
        const float bv = bsh[n];
#pragma unroll
        for (int i = 0; i < 4; i++)
            part[i] += fast_tanh(acc[i][j] + bv) * uu;
    }
#pragma unroll
    for (int off = 8; off > 0; off >>= 1) {
#pragma unroll
        for (int i = 0; i < 4; i++)
            part[i] += __shfl_xor_sync(0xffffffffu, part[i], off);
    }
    if (tx == 0) {
#pragma unroll
        for (int i = 0; i < 4; i++)
            g_scores[(size_t)b * L_ + l0 + ty * 4 + i] = part[i];
    }
}

// ---------------------------------------------------------------------------
// Kernel 2: masked softmax over l < len[b]; writes alpha back into g_scores.
// ---------------------------------------------------------------------------
__global__ __launch_bounds__(256) void softmax_kernel(const int* __restrict__ len_in)
{
    const int b   = blockIdx.x;
    const int len = len_in[b];
    const int tid = threadIdx.x;
    __shared__ float red[256];

    float m = -1e30f;
    for (int l = tid; l < len; l += 256)
        m = fmaxf(m, g_scores[(size_t)b * L_ + l]);
    red[tid] = m;
    __syncthreads();
    for (int s = 128; s > 0; s >>= 1) {
        if (tid < s) red[tid] = fmaxf(red[tid], red[tid + s]);
        __syncthreads();
    }
    const float mx = red[0];
    __syncthreads();

    float sum = 0.0f;
    for (int l = tid; l < len; l += 256)
        sum += __expf(g_scores[(size_t)b * L_ + l] - mx);
    red[tid] = sum;
    __syncthreads();
    for (int s = 128; s > 0; s >>= 1) {
        if (tid < s) red[tid] += red[tid + s];
        __syncthreads();
    }
    const float inv = __fdividef(1.0f, red[0]);

    for (int l = tid; l < len; l += 256)
        g_scores[(size_t)b * L_ + l] = __expf(g_scores[(size_t)b * L_ + l] - mx) * inv;
}

// ---------------------------------------------------------------------------
// Kernel 3: split-K weighted sum. v_part[s][b][:] = sum_{l in split s, l<len} alpha_l * h[b,l,:]
// ---------------------------------------------------------------------------
__global__ __launch_bounds__(256) void wsum_kernel(
    const float* __restrict__ hin,
    const int*   __restrict__ len_in)
{
    const int b = blockIdx.x;
    const int s = blockIdx.y;
    const int t = threadIdx.x;
    const int len = len_in[b];
    const int l0 = s * (L_ / NSPLIT);
    const int l1 = min(l0 + (L_ / NSPLIT), len);

    float acc = 0.0f;
    if (t < H_) {
        const float* hp = hin + ((size_t)b * L_ + l0) * H_ + t;
        const float* ap = g_scores + (size_t)b * L_ + l0;
        int l = l0;
#pragma unroll 4
        for (; l < l1; l++) {
            acc = fmaf(ap[l - l0], hp[(size_t)(l - l0) * H_], acc);
        }
        g_vpart[((size_t)s * B_ + b) * H_ + t] = acc;
    }
}

// ---------------------------------------------------------------------------
// Kernel 4: reduce splits into d_out.
// ---------------------------------------------------------------------------
__global__ __launch_bounds__(H_) void reduce_kernel(float* __restrict__ out)
{
    const int b = blockIdx.x;
    const int t = threadIdx.x;
    float v = 0.0f;
#pragma unroll
    for (int s = 0; s < NSPLIT; s++)
        v += g_vpart[((size_t)s * B_ + b) * H_ + t];
    out[(size_t)b * H_ + t] = v;
}

// ---------------------------------------------------------------------------
// Inputs (metadata order):
//   0: short_perference  [1,B,L,H] f32
//   1: current_perference[1,B,H]   f32
//   2: W                 [H,H]     f32
//   3: b                 [H]       f32
//   4: current_batch     scalar i32 (unused; B fixed)
//   5: length_input      [B]       i32
// Output: v [B,H] f32
// ---------------------------------------------------------------------------
extern "C" void kernel_launch(void* const* d_in, const int* in_sizes, int n_in,
                              void* d_out, int out_size)
{
    const float* hin  = (const float*)d_in[0];
    const float* us   = (const float*)d_in[1];
    const float* W    = (const float*)d_in[2];
    const float* bias = (const float*)d_in[3];
    const int*   len  = (const int*)d_in[5];
    float* out = (float*)d_out;

    scores_kernel<<<dim3(L_ / 64, B_), 256>>>(hin, us, W, bias, len);
    softmax_kernel<<<B_, 256>>>(len);
    wsum_kernel<<<dim3(B_, NSPLIT), 256>>>(hin, len);
    reduce_kernel<<<B_, H_>>>(out);
}

// round 4
// speedup vs baseline: 2.0318x; 2.0318x over previous
#include <cuda_runtime.h>
#include <cuda_bf16.h>
#include <cstdint>

#define B_ 256
#define L_ 2048
#define H_ 240
#define MT 128          // l-rows per CTA tile
#define KC 48           // K per chunk
#define KCP_B 112       // padded SMEM row stride in bytes (56 bf16)
#define NCH 5           // 5 * 48 = 240
#define NSPLIT 8

// ---------------- static scratch (allocation-free rule) ----------------
__device__ float g_scores[B_ * L_];
__device__ float g_vpart[NSPLIT * B_ * H_];
__device__ __align__(16) __nv_bfloat16 g_Whi[H_ * 256];
__device__ __align__(16) __nv_bfloat16 g_Wlo[H_ * 256];

// ---------------- helpers ----------------
__device__ __forceinline__ float ex2f(float x){ float y; asm("ex2.approx.f32 %0,%1;":"=f"(y):"f"(x)); return y; }
__device__ __forceinline__ float rcpf(float x){ float y; asm("rcp.approx.f32 %0,%1;":"=f"(y):"f"(x)); return y; }
// pack two f32 -> bf16x2; 'lo' lands in low half (element k), 'hi' in high (k+1)
__device__ __forceinline__ uint32_t bf16x2(float lo, float hi){
    uint32_t r; asm("cvt.rn.bf16x2.f32 %0, %1, %2;" : "=r"(r) : "f"(hi), "f"(lo)); return r;
}
__device__ __forceinline__ float bflo(uint32_t p){
    return __bfloat162float(__ushort_as_bfloat16((unsigned short)(p & 0xffffu)));
}
__device__ __forceinline__ float bfhi(uint32_t p){
    return __bfloat162float(__ushort_as_bfloat16((unsigned short)(p >> 16)));
}

// m16n8k16 row.col bf16 -> f32 (compute_80+ PTX; maps to HMMA on sm_100)
__device__ __forceinline__ void mma16816(float c[4], const uint32_t a[4],
                                         uint32_t b0, uint32_t b1){
    asm volatile(
        "mma.sync.aligned.m16n8k16.row.col.f32.bf16.bf16.f32 "
        "{%0,%1,%2,%3},{%4,%5,%6,%7},{%8,%9},{%0,%1,%2,%3};"
        : "+f"(c[0]), "+f"(c[1]), "+f"(c[2]), "+f"(c[3])
        : "r"(a[0]), "r"(a[1]), "r"(a[2]), "r"(a[3]), "r"(b0), "r"(b1));
}

// ---------------- SMEM layout (bytes) ----------------
#define SM_US2    0         // 240 f
#define SM_BIASC  960       // 240 f
#define SM_SC     1920      // 256 f
#define SM_RED    2944      // 8 f
#define SM_SUM    2976      // 1 f  (pad to 3072)
#define SM_AHI    3072      // 128*112 = 14336
#define SM_ALO    17408
#define SM_BHI    31744     // 240*112 = 26880
#define SM_BLO    58624
#define SMEM_SZ   85504

// ---------------- prep: split W into bf16 hi/lo ----------------
__global__ void prep_w_kernel(const float* __restrict__ W) {
    int i = blockIdx.x * 256 + threadIdx.x;
    if (i >= H_ * 256) return;
    int o = i >> 8, k = i & 255;
    float w = (k < H_) ? W[o * H_ + k] : 0.0f;
    __nv_bfloat16 hi = __float2bfloat16(w);
    __nv_bfloat16 lo = __float2bfloat16(w - __bfloat162float(hi));
    g_Whi[i] = hi; g_Wlo[i] = lo;
}

// ---------------- kernel 1: warp-MMA scores ----------------
// scores[b,l] = sum_o tanh(h[b,l,:].W[o,:] + bias[o]) * us[b,o]
__global__ __launch_bounds__(512, 1)
void scores_mma_kernel(const float* __restrict__ hin,
                       const float* __restrict__ us,
                       const float* __restrict__ bias,
                       const int*   __restrict__ len_in)
{
    const int b  = blockIdx.y;
    const int l0 = blockIdx.x * MT;
    const int len = len_in[b];
    if (l0 >= len) return;

    extern __shared__ char smem[];
    float* us2   = (float*)(smem + SM_US2);
    float* biasc = (float*)(smem + SM_BIASC);
    float* SC    = (float*)(smem + SM_SC);
    float* red   = (float*)(smem + SM_RED);

    const int tid  = threadIdx.x;
    const int wid  = tid >> 5;
    const int lane = tid & 31;
    const int wm   = wid >> 1;       // 0..7  (16 rows each)
    const int wn   = wid & 1;        // 0..1  (120 cols each)
    const int g    = lane >> 2;      // 0..7
    const int t    = lane & 3;       // 0..3
    const float C2LE = 2.8853900817779268f;   // 2*log2(e)

    // u_s-derived tables + Sum(u)
    if (tid < 256) {
        float u = (tid < H_) ? us[b * H_ + tid] : 0.0f;
        if (tid < H_) {
            us2[tid]   = -2.0f * u;
            biasc[tid] = bias[tid] * C2LE;
        }
        float uv = u;
        #pragma unroll
        for (int off = 16; off > 0; off >>= 1)
            uv += __shfl_xor_sync(0xffffffffu, uv, off);
        if (lane == 0) red[wid] = uv;
    }

    float c[15][4];
    #pragma unroll
    for (int j = 0; j < 15; j++)
        #pragma unroll
        for (int q = 0; q < 4; q++) c[j][q] = 0.0f;

    const size_t hbase = ((size_t)b * L_ + l0) * H_;

    for (int ch = 0; ch < NCH; ch++) {
        const int k0 = ch * KC;

        // ---- A chunk: 128 rows x 48 k, fp32 -> bf16 hi/lo, SMEM ----
        for (int i = tid; i < 1536; i += 512) {      // 128*12 float4
            int row = i / 12, c4 = i % 12;
            float4 v = *(const float4*)(hin + hbase + (size_t)row * H_ + k0 + c4 * 4);
            uint32_t hi01 = bf16x2(v.x, v.y);
            uint32_t hi23 = bf16x2(v.z, v.w);
            uint32_t lo01 = bf16x2(v.x - bflo(hi01), v.y - bfhi(hi01));
            uint32_t lo23 = bf16x2(v.z - bflo(hi23), v.w - bfhi(hi23));
            int off = row * KCP_B + c4 * 8;
            *(uint2*)(smem + SM_AHI + off) = make_uint2(hi01, hi23);
            *(uint2*)(smem + SM_ALO + off) = make_uint2(lo01, lo23);
        }
        // ---- B chunk: 240 rows x 48 k of pre-split W ----
        for (int i = tid; i < 1440; i += 512) {      // 240*6 uint4
            int row = i / 6, q = i % 6;
            int off = row * KCP_B + q * 16;
            *(uint4*)(smem + SM_BHI + off) = *(const uint4*)(g_Whi + row * 256 + k0 + q * 8);
            *(uint4*)(smem + SM_BLO + off) = *(const uint4*)(g_Wlo + row * 256 + k0 + q * 8);
        }
        __syncthreads();

        if (ch == 0 && tid == 0) {     // fold Sum(u) once (red[] final after sync)
            float s = 0.0f;
            #pragma unroll
            for (int w = 0; w < 8; w++) s += red[w];
            *(float*)(smem + SM_SUM) = s;
        }

        // ---- 3 k16-steps, 3 passes fused per step ----
        #pragma unroll
        for (int ks = 0; ks < 3; ks++) {
            const int kb = ks * 32;                 // byte offset of k-step (16 bf16)
            const int ra = (wm * 16 + g) * KCP_B + kb + t * 4;
            uint32_t ah[4], al[4];
            ah[0] = *(const uint32_t*)(smem + SM_AHI + ra);
            ah[1] = *(const uint32_t*)(smem + SM_AHI + ra + 8 * KCP_B);
            ah[2] = *(const uint32_t*)(smem + SM_AHI + ra + 16);
            ah[3] = *(const uint32_t*)(smem + SM_AHI + ra + 8 * KCP_B + 16);
            al[0] = *(const uint32_t*)(smem + SM_ALO + ra);
            al[1] = *(const uint32_t*)(smem + SM_ALO + ra + 8 * KCP_B);
            al[2] = *(const uint32_t*)(smem + SM_ALO + ra + 16);
            al[3] = *(const uint32_t*)(smem + SM_ALO + ra + 8 * KCP_B + 16);

            #pragma unroll
            for (int j = 0; j < 15; j++) {
                const int rb = (wn * 120 + j * 8 + g) * KCP_B + kb + t * 4;
                uint32_t bh0 = *(const uint32_t*)(smem + SM_BHI + rb);
                uint32_t bh1 = *(const uint32_t*)(smem + SM_BHI + rb + 16);
                uint32_t bl0 = *(const uint32_t*)(smem + SM_BLO + rb);
                uint32_t bl1 = *(const uint32_t*)(smem + SM_BLO + rb + 16);
                mma16816(c[j], ah, bh0, bh1);   // hi*hi
                mma16816(c[j], ah, bl0, bl1);   // hi*lo
                mma16816(c[j], al, bh0, bh1);   // lo*hi
            }
        }
        __syncthreads();   // protect SMEM before next chunk overwrites
    }

    // ---- epilogue on register fragments: u.tanh = u + us2*rcp(ex2(2x*log2e)+1) ----
    float a0 = 0.0f, a1 = 0.0f;        // rows wm*16+g and wm*16+8+g
    #pragma unroll
    for (int j = 0; j < 15; j++) {
        const int n0 = wn * 120 + j * 8 + 2 * t;
        const int n1 = n0 + 1;
        const float u0 = us2[n0], u1 = us2[n1];
        const float bb0 = biasc[n0], bb1 = biasc[n1];
        a0 = fmaf(u0, rcpf(ex2f(fmaf(c[j][0], C2LE, bb0)) + 1.0f), a0);
        a0 = fmaf(u1, rcpf(ex2f(fmaf(c[j][1], C2LE, bb1)) + 1.0f), a0);
        a1 = fmaf(u0, rcpf(ex2f(fmaf(c[j][2], C2LE, bb0)) + 1.0f), a1);
        a1 = fmaf(u1, rcpf(ex2f(fmaf(c[j][3], C2LE, bb1)) + 1.0f), a1);
    }
    // reduce across t (4 lanes share a row)
    a0 += __shfl_xor_sync(0xffffffffu, a0, 1);
    a0 += __shfl_xor_sync(0xffffffffu, a0, 2);
    a1 += __shfl_xor_sync(0xffffffffu, a1, 1);
    a1 += __shfl_xor_sync(0xffffffffu, a1, 2);
    if (t == 0) {
        SC[wn * 128 + wm * 16 + g]     = a0;
        SC[wn * 128 + wm * 16 + 8 + g] = a1;
    }
    __syncthreads();

    if (tid < MT) {
        float s = SC[tid] + SC[128 + tid] + *(float*)(smem + SM_SUM);
        g_scores[(size_t)b * L_ + l0 + tid] = s;
    }
}

// ---------------- kernel 2: masked softmax ----------------
__global__ __launch_bounds__(256) void softmax_kernel(const int* __restrict__ len_in)
{
    const int b   = blockIdx.x;
    const int len = len_in[b];
    const int tid = threadIdx.x;
    __shared__ float red[256];

    float m = -1e30f;
    for (int l = tid; l < len; l += 256)
        m = fmaxf(m, g_scores[(size_t)b * L_ + l]);
    red[tid] = m;
    __syncthreads();
    for (int s = 128; s > 0; s >>= 1) {
        if (tid < s) red[tid] = fmaxf(red[tid], red[tid + s]);
        __syncthreads();
    }
    const float mx = red[0];
    __syncthreads();

    float sum = 0.0f;
    for (int l = tid; l < len; l += 256)
        sum += __expf(g_scores[(size_t)b * L_ + l] - mx);
    red[tid] = sum;
    __syncthreads();
    for (int s = 128; s > 0; s >>= 1) {
        if (tid < s) red[tid] += red[tid + s];
        __syncthreads();
    }
    const float inv = __fdividef(1.0f, red[0]);

    for (int l = tid; l < len; l += 256)
        g_scores[(size_t)b * L_ + l] = __expf(g_scores[(size_t)b * L_ + l] - mx) * inv;
}

// ---------------- kernel 3: split-K weighted sum ----------------
__global__ __launch_bounds__(256) void wsum_kernel(
    const float* __restrict__ hin,
    const int*   __restrict__ len_in)
{
    const int b = blockIdx.x;
    const int s = blockIdx.y;
    const int t = threadIdx.x;
    const int len = len_in[b];
    const int l0 = s * (L_ / NSPLIT);
    const int l1 = min(l0 + (L_ / NSPLIT), len);

    if (t < H_) {
        float acc = 0.0f;
        const float* hp = hin + ((size_t)b * L_ + l0) * H_ + t;
        const float* ap = g_scores + (size_t)b * L_ + l0;
        #pragma unroll 4
        for (int l = l0; l < l1; l++)
            acc = fmaf(ap[l - l0], hp[(size_t)(l - l0) * H_], acc);
        g_vpart[((size_t)s * B_ + b) * H_ + t] = acc;
    }
}

// ---------------- kernel 4: reduce splits ----------------
__global__ __launch_bounds__(H_) void reduce_kernel(float* __restrict__ out)
{
    const int b = blockIdx.x;
    const int t = threadIdx.x;
    float v = 0.0f;
    #pragma unroll
    for (int s = 0; s < NSPLIT; s++)
        v += g_vpart[((size_t)s * B_ + b) * H_ + t];
    out[(size_t)b * H_ + t] = v;
}

// ---------------- launch ----------------
extern "C" void kernel_launch(void* const* d_in, const int* in_sizes, int n_in,
                              void* d_out, int out_size)
{
    const float* hin  = (const float*)d_in[0];
    const float* us   = (const float*)d_in[1];
    const float* W    = (const float*)d_in[2];
    const float* bias = (const float*)d_in[3];
    const int*   len  = (const int*)d_in[5];
    float* out = (float*)d_out;

    cudaFuncSetAttribute(scores_mma_kernel,
                         cudaFuncAttributeMaxDynamicSharedMemorySize, SMEM_SZ);

    prep_w_kernel<<<(H_ * 256 + 255) / 256, 256>>>(W);
    scores_mma_kernel<<<dim3(L_ / MT, B_), 512, SMEM_SZ>>>(hin, us, bias, len);
    softmax_kernel<<<B_, 256>>>(len);
    wsum_kernel<<<dim3(B_, NSPLIT), 256>>>(hin, len);
    reduce_kernel<<<B_, H_>>>(out);
}